// round 1
// baseline (speedup 1.0000x reference)
#include <cuda_runtime.h>

#define NT   128          // n*t
#define CH   256          // channels
#define HW   196          // h*w = 14*14
#define ICN  64           // inter_channels
#define OUTW 448          // 14*32
#define MASK_ELEMS (NT*2*OUTW*OUTW)   // 51,380,224

// Scratch (no allocations allowed; __device__ globals per harness rules)
__device__ float g_Y[NT*ICN*HW];   // raw linear Wq @ x  (no bias), 6.4 MB
__device__ float g_v[NT*HW];       // value per (n, hw)
__device__ float g_m[NT*HW];       // sigmoid(attn @ v) per (n, hw)

// ---------------------------------------------------------------------------
// Kernel 1: Y[n][d][i] = sum_c Wq[d][c] * x[n][c][i]   (d<64, c<256, i<196)
// One block per n. 224 threads, each computes an 8x7 register tile.
// ---------------------------------------------------------------------------
__global__ __launch_bounds__(224) void k_linear(const float* __restrict__ x,
                                                const float* __restrict__ Wq)
{
    __shared__ float Xs[32*HW];    // 32 channels x 196
    __shared__ float Ws[32*ICN];   // 32 channels x 64 (transposed Wq tile)
    const int n   = blockIdx.x;
    const int tid = threadIdx.x;
    const int ty  = tid / 28;      // 0..7 -> d rows [ty*8, ty*8+7]
    const int tx  = tid % 28;      // 0..27 -> cols  [tx*7, tx*7+6]

    float acc[8][7];
#pragma unroll
    for (int r = 0; r < 8; r++)
#pragma unroll
        for (int j = 0; j < 7; j++) acc[r][j] = 0.f;

    const float* xb = x + (size_t)n * CH * HW;

    for (int kc = 0; kc < CH; kc += 32) {
        __syncthreads();
        // x chunk is fully contiguous: [kc..kc+32) x 196
        for (int idx = tid; idx < 32*HW; idx += 224)
            Xs[idx] = xb[kc*HW + idx];
        // Wq tile, transposed to [cc][d]
        for (int idx = tid; idx < 32*ICN; idx += 224) {
            int cc = idx >> 6, d = idx & 63;
            Ws[idx] = Wq[d*257 + kc + cc];
        }
        __syncthreads();

#pragma unroll 4
        for (int cc = 0; cc < 32; cc++) {
            float a[8], b[7];
#pragma unroll
            for (int r = 0; r < 8; r++) a[r] = Ws[cc*ICN + ty*8 + r];
#pragma unroll
            for (int j = 0; j < 7; j++) b[j] = Xs[cc*HW + tx*7 + j];
#pragma unroll
            for (int r = 0; r < 8; r++)
#pragma unroll
                for (int j = 0; j < 7; j++)
                    acc[r][j] = fmaf(a[r], b[j], acc[r][j]);
        }
    }

    float* yb = g_Y + (size_t)n * ICN * HW;
#pragma unroll
    for (int r = 0; r < 8; r++)
#pragma unroll
        for (int j = 0; j < 7; j++)
            yb[(ty*8 + r)*HW + tx*7 + j] = acc[r][j];
}

// ---------------------------------------------------------------------------
// Kernel 1b: v[n][i] = sum_{c<256} Wv[c]*x[sn][c][i] - Wv[256]*(lam-.5) + bv
// Also writes v_out tail of d_out (identical layout [16,8,14,14] = [128,196]).
// ---------------------------------------------------------------------------
__global__ __launch_bounds__(196) void k_value(const float* __restrict__ x,
                                               const float* __restrict__ Wv,
                                               const float* __restrict__ bv,
                                               const float* __restrict__ lam,
                                               const int*   __restrict__ index,
                                               float*       __restrict__ vtail)
{
    const int n  = blockIdx.x;
    const int i  = threadIdx.x;                       // 0..195
    const int sn = index[n >> 3] * 8 + (n & 7);       // shuffled partner row
    const float* xb = x + (size_t)sn * CH * HW + i;

    float a0 = 0.f, a1 = 0.f, a2 = 0.f, a3 = 0.f;
#pragma unroll 4
    for (int c = 0; c < CH; c += 4) {
        a0 = fmaf(Wv[c+0], xb[(c+0)*HW], a0);
        a1 = fmaf(Wv[c+1], xb[(c+1)*HW], a1);
        a2 = fmaf(Wv[c+2], xb[(c+2)*HW], a2);
        a3 = fmaf(Wv[c+3], xb[(c+3)*HW], a3);
    }
    const float lamv = lam[0] - 0.5f;
    const float v = (a0 + a1) + (a2 + a3) - Wv[CH]*lamv + bv[0];
    g_v[n*HW + i]  = v;
    vtail[n*HW + i] = v;
}

// ---------------------------------------------------------------------------
// Kernel 2: per-n attention. scores = (q/8)^T k, softmax over j, dot with v,
// sigmoid -> g_m. q/k built from shared Y with +/- lam-channel bias terms.
// ---------------------------------------------------------------------------
__global__ __launch_bounds__(256) void k_attn(const float* __restrict__ Wq,
                                              const float* __restrict__ bq,
                                              const float* __restrict__ lam,
                                              const int*   __restrict__ index)
{
    extern __shared__ float sm[];
    float* qs = sm;               // [64][196], pre-scaled by 1/8
    float* ks = qs + ICN*HW;      // [64][224], zero-padded cols 196..223
    float* vs = ks + ICN*224;     // [224], zero-padded
    __shared__ float qadd[64], kadd[64];

    const int n   = blockIdx.x;
    const int tid = threadIdx.x;
    const float lamv = lam[0] - 0.5f;

    if (tid < 64) {
        const float t = Wq[tid*257 + 256] * lamv;
        const float b = bq[tid];
        qadd[tid] = b + t;
        kadd[tid] = b - t;
    }
    __syncthreads();

    const int sn = index[n >> 3] * 8 + (n & 7);
    const float* Yq = g_Y + (size_t)n  * ICN * HW;
    const float* Yk = g_Y + (size_t)sn * ICN * HW;

    for (int idx = tid; idx < ICN*HW; idx += 256) {
        int d = idx / HW;
        qs[idx] = (Yq[idx] + qadd[d]) * 0.125f;   // fold 1/sqrt(64)
    }
    for (int idx = tid; idx < ICN*224; idx += 256) {
        int d = idx / 224, j = idx % 224;
        ks[idx] = (j < HW) ? (Yk[d*HW + j] + kadd[d]) : 0.f;
    }
    for (int idx = tid; idx < 224; idx += 256)
        vs[idx] = (idx < HW) ? g_v[n*HW + idx] : 0.f;
    __syncthreads();

    const int warp = tid >> 5, lane = tid & 31;

    for (int it = 0; it < 7; it++) {
        const int i0 = it*32 + warp*4;            // 4 query rows per warp
        if (i0 >= HW) continue;                   // warp-uniform

        float acc[4][7];
#pragma unroll
        for (int r = 0; r < 4; r++)
#pragma unroll
            for (int g = 0; g < 7; g++) acc[r][g] = 0.f;

#pragma unroll 2
        for (int d = 0; d < ICN; d++) {
            float kv[7];
#pragma unroll
            for (int g = 0; g < 7; g++) kv[g] = ks[d*224 + lane + 32*g];
            float qv[4];
#pragma unroll
            for (int r = 0; r < 4; r++) qv[r] = qs[d*HW + i0 + r]; // broadcast
#pragma unroll
            for (int r = 0; r < 4; r++)
#pragma unroll
                for (int g = 0; g < 7; g++)
                    acc[r][g] = fmaf(qv[r], kv[g], acc[r][g]);
        }

#pragma unroll
        for (int r = 0; r < 4; r++) {
            const int i = i0 + r;                 // always < 196 here
            float mx = -1e30f;
#pragma unroll
            for (int g = 0; g < 7; g++) {
                float s = (lane + 32*g < HW) ? acc[r][g] : -1e30f;
                acc[r][g] = s;
                mx = fmaxf(mx, s);
            }
#pragma unroll
            for (int o = 16; o > 0; o >>= 1)
                mx = fmaxf(mx, __shfl_xor_sync(0xffffffffu, mx, o));

            float se = 0.f, pv = 0.f;
#pragma unroll
            for (int g = 0; g < 7; g++) {
                float e = __expf(acc[r][g] - mx); // masked cols -> 0
                se += e;
                pv = fmaf(e, vs[lane + 32*g], pv);
            }
#pragma unroll
            for (int o = 16; o > 0; o >>= 1) {
                se += __shfl_xor_sync(0xffffffffu, se, o);
                pv += __shfl_xor_sync(0xffffffffu, pv, o);
            }
            if (lane == 0) {
                float z = pv / se;
                g_m[n*HW + i] = 1.f / (1.f + __expf(-z));
            }
        }
    }
}

// ---------------------------------------------------------------------------
// Kernel 3: 32x nearest upsample + channel concat [1-m, m]. Pure store BW.
// blockDim (112,4): x4 = threadIdx.x (float4 column), 4 y-rows per block.
// gridDim (112, 256): blockIdx.x = y-group, blockIdx.y = n*2+ch.
// ---------------------------------------------------------------------------
__global__ __launch_bounds__(448) void k_mask(float4* __restrict__ out)
{
    const int x4 = threadIdx.x;                       // 0..111
    const int y  = blockIdx.x*4 + threadIdx.y;        // 0..447
    const int nc = blockIdx.y;                        // n*2+ch
    const int n  = nc >> 1, ch = nc & 1;

    const int cell = (y >> 5)*14 + (x4 >> 3);         // (y/32, x/32)
    const float m  = g_m[n*HW + cell];
    const float v  = ch ? m : (1.0f - m);
    out[(nc*OUTW + y)*112 + x4] = make_float4(v, v, v, v);
}

// ---------------------------------------------------------------------------
extern "C" void kernel_launch(void* const* d_in, const int* in_sizes, int n_in,
                              void* d_out, int out_size)
{
    const float* x     = (const float*)d_in[0];  // [16,8,256,14,14]
    const float* lam   = (const float*)d_in[1];  // scalar
    const int*   index = (const int*)  d_in[2];  // [16]
    const float* Wq    = (const float*)d_in[3];  // [64,257]
    const float* bq    = (const float*)d_in[4];  // [64]
    const float* Wv    = (const float*)d_in[5];  // [1,257]
    const float* bv    = (const float*)d_in[6];  // [1]

    float* out   = (float*)d_out;
    float* vtail = out + MASK_ELEMS;             // v_out after mask

    k_linear<<<NT, 224>>>(x, Wq);
    k_value <<<NT, 196>>>(x, Wv, bv, lam, index, vtail);

    const int smem2 = (ICN*HW + ICN*224 + 224) * (int)sizeof(float); // 108,416 B
    cudaFuncSetAttribute(k_attn, cudaFuncAttributeMaxDynamicSharedMemorySize, smem2);
    k_attn<<<NT, 256, smem2>>>(Wq, bq, lam, index);

    k_mask<<<dim3(112, 256), dim3(112, 4)>>>((float4*)d_out);
}